// round 2
// baseline (speedup 1.0000x reference)
#include <cuda_runtime.h>
#include <math.h>

// Problem constants: output_spikes (B=16, T=2000, N=512) float32, target_cv (512) float32.
#define NNEUR 512
#define LTOT  32000            // B*T
#define NCHUNK 256
#define ROWS  (LTOT / NCHUNK)  // 125

// Per-(chunk, neuron) partial: {k, first_spike_l, last_spike_l, bits(sum_d2)}
__device__ int4 g_partial[NCHUNK * NNEUR];

__global__ __launch_bounds__(NNEUR) void cv_pass1(const float* __restrict__ x) {
    const int n = threadIdx.x;     // neuron
    const int c = blockIdx.x;      // chunk
    const int base = c * ROWS;

    int k = 0, first = 0, last = 0;
    float s = 0.0f;

    const float* p = x + (size_t)base * NNEUR + n;
#pragma unroll 5
    for (int r = 0; r < ROWS; ++r) {
        float v = p[(size_t)r * NNEUR];
        if (v > 0.0f) {
            int l = base + r;
            if (k == 0) {
                first = l;
            } else {
                int d = l - last;
                s += (float)(d * d);
            }
            last = l;
            ++k;
        }
    }
    g_partial[c * NNEUR + n] = make_int4(k, first, last, __float_as_int(s));
}

__global__ __launch_bounds__(NNEUR) void cv_pass2(const float* __restrict__ target,
                                                  float* __restrict__ out) {
    const int n = threadIdx.x;     // neuron

    int k = 0, first = 0, last = 0;
    float s = 0.0f;

    for (int c = 0; c < NCHUNK; ++c) {
        int4 part = g_partial[c * NNEUR + n];
        int pk = part.x;
        if (pk > 0) {
            if (k == 0) {
                first = part.y;
            } else {
                int d = part.y - last;     // cross-chunk ISI
                s += (float)d * (float)d;
            }
            s += __int_as_float(part.w);   // within-chunk sum of d^2
            last = part.z;
            k += pk;
        }
    }

    float sq = 0.0f;
    int valid = 0;
    if (k >= 3) {
        float cnt = (float)(k - 1);                 // number of ISIs
        float sum_d = (float)(last - first);        // telescoping sum of ISIs
        float mean = sum_d / cnt;
        if (mean > 0.0f) {
            valid = 1;
            // sum((d - mean)^2) = sum_d2 - 2*mean*sum_d + cnt*mean^2
            float var = (s - 2.0f * mean * sum_d + cnt * mean * mean)
                        / fmaxf(cnt - 1.0f, 1.0f);  // unbiased (correction=1)
            float stdv = (var > 0.0f) ? sqrtf(var) : 0.0f;
            float cv = stdv / fmaxf(mean, 1e-12f);
            float diff = cv - target[n];
            sq = diff * diff;
        }
    }

    __shared__ float ssum[NNEUR];
    __shared__ int scnt[NNEUR];
    ssum[n] = sq;
    scnt[n] = valid;
    __syncthreads();
#pragma unroll
    for (int stride = NNEUR / 2; stride > 0; stride >>= 1) {
        if (n < stride) {
            ssum[n] += ssum[n + stride];
            scnt[n] += scnt[n + stride];
        }
        __syncthreads();
    }
    if (n == 0) {
        out[0] = ssum[0] / fmaxf((float)scnt[0], 1.0f);
    }
}

extern "C" void kernel_launch(void* const* d_in, const int* in_sizes, int n_in,
                              void* d_out, int out_size) {
    const float* spikes = (const float*)d_in[0];   // (16, 2000, 512) float32
    const float* target = (const float*)d_in[1];   // (512,) float32
    float* out = (float*)d_out;                    // scalar float32

    cv_pass1<<<NCHUNK, NNEUR>>>(spikes);
    cv_pass2<<<1, NNEUR>>>(target, out);
}

// round 4
// speedup vs baseline: 2.1220x; 2.1220x over previous
#include <cuda_runtime.h>
#include <math.h>

// output_spikes (B=16, T=2000, N=512) float32, target_cv (512) float32.
#define NNEUR 512
#define LTOT  32000                 // B*T
#define NCHUNK 148                  // one block per SM, single wave
#define ROWS_BASE (LTOT / NCHUNK)   // 216
#define ROWS_REM  (LTOT % NCHUNK)   // 32 (chunks 0..31 get 217 rows)
#define RED_THREADS 256             // pow2 >= NCHUNK for the tree

// Per-(chunk, neuron) partial: {k, first_spike_l, last_spike_l, bits(sum_d2)}
__device__ int4  g_partial[NCHUNK * NNEUR];
__device__ float g_accum;
__device__ int   g_cnt;

__global__ __launch_bounds__(NNEUR) void cv_pass1(const float* __restrict__ x) {
    const int n = threadIdx.x;     // neuron
    const int c = blockIdx.x;      // chunk
    if (c == 0 && n == 0) { g_accum = 0.0f; g_cnt = 0; }   // read only by later launches

    const int start = c * ROWS_BASE + min(c, ROWS_REM);
    const int rows  = ROWS_BASE + (c < ROWS_REM ? 1 : 0);

    int k = 0, first = 0, last = 0;
    float s = 0.0f;

    const float* p = x + (size_t)start * NNEUR + n;
#pragma unroll 8
    for (int r = 0; r < rows; ++r) {
        float v = p[(size_t)r * NNEUR];
        if (v > 0.0f) {
            int l = start + r;
            if (k == 0) {
                first = l;
            } else {
                int d = l - last;
                s += (float)(d * d);
            }
            last = l;
            ++k;
        }
    }
    g_partial[c * NNEUR + n] = make_int4(k, first, last, __float_as_int(s));
}

// One block per neuron. Adjacent-pair tree: slot t <- combine(slot 2t, slot 2t+1),
// so each slot always covers a CONTIGUOUS range of chunks (combine is ordered-
// associative, not commutative).
__global__ __launch_bounds__(RED_THREADS) void cv_pass2(const float* __restrict__ target) {
    const int n   = blockIdx.x;    // neuron
    const int tid = threadIdx.x;

    __shared__ int   sk[RED_THREADS];
    __shared__ int   sf[RED_THREADS];
    __shared__ int   sl[RED_THREADS];
    __shared__ float ss[RED_THREADS];

    int k = 0, first = 0, last = 0;
    float s = 0.0f;
    if (tid < NCHUNK) {
        int4 part = g_partial[tid * NNEUR + n];
        k = part.x; first = part.y; last = part.z; s = __int_as_float(part.w);
    }
    sk[tid] = k; sf[tid] = first; sl[tid] = last; ss[tid] = s;
    __syncthreads();

    for (int lvl = RED_THREADS; lvl > 1; lvl >>= 1) {
        const int half = lvl >> 1;
        int ak = 0, af = 0, al = 0, bk = 0, bf = 0, bl = 0;
        float as = 0.0f, bs = 0.0f;
        if (tid < half) {
            const int i = 2 * tid;
            ak = sk[i];     af = sf[i];     al = sl[i];     as = ss[i];
            bk = sk[i + 1]; bf = sf[i + 1]; bl = sl[i + 1]; bs = ss[i + 1];
        }
        __syncthreads();
        if (tid < half) {
            int   rk, rf, rl;
            float rs;
            if (bk == 0) {
                rk = ak; rf = af; rl = al; rs = as;
            } else if (ak == 0) {
                rk = bk; rf = bf; rl = bl; rs = bs;
            } else {
                float d = (float)(bf - al);      // cross-segment ISI (segments adjacent)
                rk = ak + bk;
                rf = af;
                rl = bl;
                rs = as + bs + d * d;
            }
            sk[tid] = rk; sf[tid] = rf; sl[tid] = rl; ss[tid] = rs;
        }
        __syncthreads();
    }

    if (tid == 0) {
        int kk = sk[0];
        if (kk >= 3) {
            float cnt   = (float)(kk - 1);            // number of ISIs
            float sum_d = (float)(sl[0] - sf[0]);     // telescoping sum of ISIs
            float mean  = sum_d / cnt;
            if (mean > 0.0f) {
                // sum((d-mean)^2) = sum_d2 - 2*mean*sum_d + cnt*mean^2
                float var = (ss[0] - 2.0f * mean * sum_d + cnt * mean * mean)
                            / fmaxf(cnt - 1.0f, 1.0f);   // unbiased (correction=1)
                float stdv = (var > 0.0f) ? sqrtf(var) : 0.0f;
                float cv   = stdv / fmaxf(mean, 1e-12f);
                float diff = cv - target[n];
                atomicAdd(&g_accum, diff * diff);
                atomicAdd(&g_cnt, 1);
            }
        }
    }
}

__global__ void cv_pass3(float* __restrict__ out) {
    out[0] = g_accum / fmaxf((float)g_cnt, 1.0f);
}

extern "C" void kernel_launch(void* const* d_in, const int* in_sizes, int n_in,
                              void* d_out, int out_size) {
    const float* spikes = (const float*)d_in[0];   // (16, 2000, 512) float32
    const float* target = (const float*)d_in[1];   // (512,) float32
    float* out = (float*)d_out;                    // scalar float32

    cv_pass1<<<NCHUNK, NNEUR>>>(spikes);
    cv_pass2<<<NNEUR, RED_THREADS>>>(target);
    cv_pass3<<<1, 1>>>(out);
}

// round 5
// speedup vs baseline: 2.4168x; 1.1389x over previous
#include <cuda_runtime.h>
#include <math.h>

// output_spikes (B=16, T=2000, N=512) float32, target_cv (512) float32.
#define NNEUR 512
#define NG    128                  // neuron groups of 4 (float4)
#define LTOT  32000                // B*T
#define NBLK  296                  // 2 blocks/SM, single wave
#define SUBS  (NBLK * 4)           // 1184 sub-chunks (4 row-slices per block)
#define RB    (LTOT / SUBS)        // 27
#define RREM  (LTOT % SUBS)        // 32 (sub-chunks 0..31 get 28 rows)
#define RED_THREADS 512            // pow2 >= NBLK for the pass-2 tree

// Per-(neuron, block) partial: {k, first_spike_l, last_spike_l, bits(sum_d2)}
// Transposed layout so pass-2 loads are coalesced along the chunk axis.
__device__ int4  g_partial[NNEUR * NBLK];
__device__ float g_accum;
__device__ int   g_cnt;

// Ordered combine of two ADJACENT segments (a before b). Identity: k == 0.
__device__ __forceinline__ int4 comb(int4 a, int4 b) {
    if (b.x == 0) return a;
    if (a.x == 0) return b;
    float d = (float)(b.y - a.z);                       // cross-segment ISI
    float s = __int_as_float(a.w) + __int_as_float(b.w) + d * d;
    return make_int4(a.x + b.x, a.y, b.z, __float_as_int(s));
}

#define PROC(vv, jj, ll)                                    \
    do {                                                    \
        if ((vv) > 0.0f) {                                  \
            int l_ = (ll);                                  \
            if (k[jj] == 0) {                               \
                first[jj] = l_;                             \
            } else {                                        \
                int d_ = l_ - last[jj];                     \
                s[jj] += (float)(d_ * d_);                  \
            }                                               \
            last[jj] = l_;                                  \
            ++k[jj];                                        \
        }                                                   \
    } while (0)

#define PROC4(v, ll)            \
    do {                        \
        PROC((v).x, 0, (ll));   \
        PROC((v).y, 1, (ll));   \
        PROC((v).z, 2, (ll));   \
        PROC((v).w, 3, (ll));   \
    } while (0)

__global__ __launch_bounds__(512, 2) void cv_pass1(const float* __restrict__ x) {
    const int tid   = threadIdx.x;
    const int slice = tid >> 7;          // 0..3 : row-slice within block
    const int g     = tid & (NG - 1);    // 0..127: neuron group (4 neurons)
    const int sc    = blockIdx.x * 4 + slice;      // global sub-chunk
    if (blockIdx.x == 0 && tid == 0) { g_accum = 0.0f; g_cnt = 0; }

    const int start = sc * RB + min(sc, RREM);
    const int rows  = RB + (sc < RREM ? 1 : 0);

    int   k[4]     = {0, 0, 0, 0};
    int   first[4] = {0, 0, 0, 0};
    int   last[4]  = {0, 0, 0, 0};
    float s[4]     = {0.0f, 0.0f, 0.0f, 0.0f};

    const float4* p = (const float4*)x + (size_t)start * NG + g;
    int r = 0;
    // batch 4 rows: 4 independent LDG.128 issued back-to-back (MLP >= 4)
    for (; r + 4 <= rows; r += 4) {
        float4 v0 = p[0 * NG];
        float4 v1 = p[1 * NG];
        float4 v2 = p[2 * NG];
        float4 v3 = p[3 * NG];
        PROC4(v0, start + r + 0);
        PROC4(v1, start + r + 1);
        PROC4(v2, start + r + 2);
        PROC4(v3, start + r + 3);
        p += 4 * NG;
    }
    for (; r < rows; ++r) {
        float4 v = p[0];
        PROC4(v, start + r);
        p += NG;
    }

    // Combine the 4 row-slices (contiguous sub-chunks, in order) in smem.
    __shared__ int4 sp[4][NNEUR];
#pragma unroll
    for (int j = 0; j < 4; ++j)
        sp[slice][g * 4 + j] = make_int4(k[j], first[j], last[j], __float_as_int(s[j]));
    __syncthreads();

    if (slice == 0) {
#pragma unroll
        for (int j = 0; j < 4; ++j) {
            const int n = g * 4 + j;
            int4 a = sp[0][n];
            a = comb(a, sp[1][n]);
            a = comb(a, sp[2][n]);
            a = comb(a, sp[3][n]);
            g_partial[(size_t)n * NBLK + blockIdx.x] = a;
        }
    }
}

// One block per neuron: adjacent-pair tree over the 296 block partials.
__global__ __launch_bounds__(RED_THREADS) void cv_pass2(const float* __restrict__ target) {
    const int n   = blockIdx.x;
    const int tid = threadIdx.x;

    __shared__ int4 sm[RED_THREADS];

    int4 part = make_int4(0, 0, 0, 0);
    if (tid < NBLK)
        part = g_partial[(size_t)n * NBLK + tid];   // coalesced along chunk axis
    sm[tid] = part;
    __syncthreads();

    for (int lvl = RED_THREADS; lvl > 1; lvl >>= 1) {
        const int half = lvl >> 1;
        int4 res;
        if (tid < half)
            res = comb(sm[2 * tid], sm[2 * tid + 1]);   // adjacent -> contiguous
        __syncthreads();
        if (tid < half)
            sm[tid] = res;
        __syncthreads();
    }

    if (tid == 0) {
        int4 tot = sm[0];
        int kk = tot.x;
        if (kk >= 3) {
            float cnt   = (float)(kk - 1);            // number of ISIs
            float sum_d = (float)(tot.z - tot.y);     // telescoping sum of ISIs
            float mean  = sum_d / cnt;
            if (mean > 0.0f) {
                // sum((d-mean)^2) = sum_d2 - 2*mean*sum_d + cnt*mean^2
                float var = (__int_as_float(tot.w) - 2.0f * mean * sum_d + cnt * mean * mean)
                            / fmaxf(cnt - 1.0f, 1.0f);   // unbiased (correction=1)
                float stdv = (var > 0.0f) ? sqrtf(var) : 0.0f;
                float cv   = stdv / fmaxf(mean, 1e-12f);
                float diff = cv - target[n];
                atomicAdd(&g_accum, diff * diff);
                atomicAdd(&g_cnt, 1);
            }
        }
    }
}

__global__ void cv_pass3(float* __restrict__ out) {
    out[0] = g_accum / fmaxf((float)g_cnt, 1.0f);
}

extern "C" void kernel_launch(void* const* d_in, const int* in_sizes, int n_in,
                              void* d_out, int out_size) {
    const float* spikes = (const float*)d_in[0];   // (16, 2000, 512) float32
    const float* target = (const float*)d_in[1];   // (512,) float32
    float* out = (float*)d_out;                    // scalar float32

    cv_pass1<<<NBLK, 512>>>(spikes);
    cv_pass2<<<NNEUR, RED_THREADS>>>(target);
    cv_pass3<<<1, 1>>>(out);
}

// round 6
// speedup vs baseline: 2.4293x; 1.0052x over previous
#include <cuda_runtime.h>
#include <math.h>

// output_spikes (B=16, T=2000, N=512) float32, target_cv (512) float32.
#define NNEUR 512
#define NG    128                  // neuron groups of 4 (float4)
#define LTOT  32000                // B*T
#define NBLK  296                  // 2 blocks/SM, single wave
#define SUBS  (NBLK * 4)           // 1184 sub-chunks (4 row-slices per block)
#define RB    (LTOT / SUBS)        // 27
#define RREM  (LTOT % SUBS)        // 32 (sub-chunks 0..31 get 28 rows)
#define RED_THREADS 512            // pow2 >= NBLK for the pass-2 tree
#define BIGF  1.0e6f               // sentinel for first-spike min trick

// Per-(neuron, block) partial: {k, first_spike_l, last_spike_l, bits(sum_d2)}
__device__ int4  g_partial[NNEUR * NBLK];
__device__ float g_accum;
__device__ int   g_cnt;

// Ordered combine of two ADJACENT segments (a before b). Identity: k == 0.
__device__ __forceinline__ int4 comb(int4 a, int4 b) {
    if (b.x == 0) return a;
    if (a.x == 0) return b;
    float d = (float)(b.y - a.z);                       // cross-segment ISI
    float s = __int_as_float(a.w) + __int_as_float(b.w) + d * d;
    return make_int4(a.x + b.x, a.y, b.z, __float_as_int(s));
}

// Branchless float update for one element. v in {0,1}. rel = 1-based local row.
// relmB = rel - BIGF (precomputed per row). All quantities exact in fp32.
#define PE(v, j, rel, relmB)                                 \
    do {                                                     \
        float d_ = (rel) - tl[j];                            \
        s[j]  = fmaf((v), d_ * d_, s[j]);                    \
        kf[j] += (v);                                        \
        tl[j] = fmaxf(tl[j], (v) * (rel));                   \
        tf[j] = fminf(tf[j], fmaf((v), (relmB), BIGF));      \
    } while (0)

#define P4(vec, rel, relmB)                 \
    do {                                    \
        PE((vec).x, 0, (rel), (relmB));     \
        PE((vec).y, 1, (rel), (relmB));     \
        PE((vec).z, 2, (rel), (relmB));     \
        PE((vec).w, 3, (rel), (relmB));     \
    } while (0)

#define PROW(vec, rr)                               \
    do {                                            \
        float rel_   = (float)((rr) + 1);           \
        float relmB_ = rel_ - BIGF;                 \
        P4((vec), rel_, relmB_);                    \
    } while (0)

__global__ __launch_bounds__(512, 2) void cv_pass1(const float* __restrict__ x) {
    const int tid   = threadIdx.x;
    const int slice = tid >> 7;          // 0..3 : row-slice within block
    const int g     = tid & (NG - 1);    // 0..127: neuron group (4 neurons)
    const int sc    = blockIdx.x * 4 + slice;      // global sub-chunk
    if (blockIdx.x == 0 && tid == 0) { g_accum = 0.0f; g_cnt = 0; }

    const int start = sc * RB + min(sc, RREM);
    const int rows  = RB + (sc < RREM ? 1 : 0);    // 27 or 28

    float kf[4] = {0.f, 0.f, 0.f, 0.f};
    float tl[4] = {0.f, 0.f, 0.f, 0.f};                 // running last (1-based local)
    float tf[4] = {BIGF, BIGF, BIGF, BIGF};             // running first
    float s[4]  = {0.f, 0.f, 0.f, 0.f};                 // sum d^2 (incl. bogus first term)

    const float4* p = (const float4*)x + (size_t)start * NG + g;
    int r = 0;

    // prefetch batch 0 (rows >= 27 > 4 always)
    float4 b0 = p[0 * NG], b1 = p[1 * NG], b2 = p[2 * NG], b3 = p[3 * NG];
    p += 4 * NG;

    while (r + 8 <= rows) {
        // prefetch next batch BEFORE processing current (loads stay in flight)
        float4 c0 = p[0 * NG], c1 = p[1 * NG], c2 = p[2 * NG], c3 = p[3 * NG];
        p += 4 * NG;
        PROW(b0, r + 0); PROW(b1, r + 1); PROW(b2, r + 2); PROW(b3, r + 3);
        b0 = c0; b1 = c1; b2 = c2; b3 = c3;
        r += 4;
    }
    // drain the prefetched batch (rows - r in [4,7])
    PROW(b0, r + 0); PROW(b1, r + 1); PROW(b2, r + 2); PROW(b3, r + 3);
    r += 4;
    // scalar tail (0..3 rows)
    for (; r < rows; ++r) {
        float4 v = p[0];
        p += NG;
        PROW(v, r);
    }

    // Convert float state -> int4 partial (local 1-based -> global 0-based).
    __shared__ int4 sp[4][NNEUR];
#pragma unroll
    for (int j = 0; j < 4; ++j) {
        int kk = (int)kf[j];
        int4 part;
        if (kk > 0) {
            float sc_ = s[j] - tf[j] * tf[j];  // remove bogus first-spike ISI (tf-0)^2
            part = make_int4(kk,
                             start + (int)tf[j] - 1,
                             start + (int)tl[j] - 1,
                             __float_as_int(sc_));
        } else {
            part = make_int4(0, 0, 0, 0);
        }
        sp[slice][g * 4 + j] = part;
    }
    __syncthreads();

    if (slice == 0) {
#pragma unroll
        for (int j = 0; j < 4; ++j) {
            const int n = g * 4 + j;
            int4 a = sp[0][n];
            a = comb(a, sp[1][n]);
            a = comb(a, sp[2][n]);
            a = comb(a, sp[3][n]);
            g_partial[(size_t)n * NBLK + blockIdx.x] = a;
        }
    }
}

// One block per neuron: adjacent-pair tree over the 296 block partials.
__global__ __launch_bounds__(RED_THREADS) void cv_pass2(const float* __restrict__ target) {
    const int n   = blockIdx.x;
    const int tid = threadIdx.x;

    __shared__ int4 sm[RED_THREADS];

    int4 part = make_int4(0, 0, 0, 0);
    if (tid < NBLK)
        part = g_partial[(size_t)n * NBLK + tid];   // coalesced along chunk axis
    sm[tid] = part;
    __syncthreads();

    for (int lvl = RED_THREADS; lvl > 1; lvl >>= 1) {
        const int half = lvl >> 1;
        int4 res;
        if (tid < half)
            res = comb(sm[2 * tid], sm[2 * tid + 1]);   // adjacent -> contiguous
        __syncthreads();
        if (tid < half)
            sm[tid] = res;
        __syncthreads();
    }

    if (tid == 0) {
        int4 tot = sm[0];
        int kk = tot.x;
        if (kk >= 3) {
            float cnt   = (float)(kk - 1);            // number of ISIs
            float sum_d = (float)(tot.z - tot.y);     // telescoping sum of ISIs
            float mean  = sum_d / cnt;
            if (mean > 0.0f) {
                // sum((d-mean)^2) = sum_d2 - 2*mean*sum_d + cnt*mean^2
                float var = (__int_as_float(tot.w) - 2.0f * mean * sum_d + cnt * mean * mean)
                            / fmaxf(cnt - 1.0f, 1.0f);   // unbiased (correction=1)
                float stdv = (var > 0.0f) ? sqrtf(var) : 0.0f;
                float cv   = stdv / fmaxf(mean, 1e-12f);
                float diff = cv - target[n];
                atomicAdd(&g_accum, diff * diff);
                atomicAdd(&g_cnt, 1);
            }
        }
    }
}

__global__ void cv_pass3(float* __restrict__ out) {
    out[0] = g_accum / fmaxf((float)g_cnt, 1.0f);
}

extern "C" void kernel_launch(void* const* d_in, const int* in_sizes, int n_in,
                              void* d_out, int out_size) {
    const float* spikes = (const float*)d_in[0];   // (16, 2000, 512) float32
    const float* target = (const float*)d_in[1];   // (512,) float32
    float* out = (float*)d_out;                    // scalar float32

    cv_pass1<<<NBLK, 512>>>(spikes);
    cv_pass2<<<NNEUR, RED_THREADS>>>(target);
    cv_pass3<<<1, 1>>>(out);
}